// round 5
// baseline (speedup 1.0000x reference)
#include <cuda_runtime.h>

#define NLEV 4
#define KCB  256
#define DIM  128
#define ROWS 64
#define TPB  256

// Scratch (allocation-free rule: __device__ globals).
// g_cbT: codebook transposed per level: [l][k][e]  (so the per-level smem copy
// is fully coalesced and the GEMM reads entry-pairs contiguously)
__device__ float g_cbT[NLEV * DIM * KCB];
__device__ float g_cnorm[NLEV * KCB];

// ---------------------------------------------------------------------------
// Prep: build transposed codebook + per-entry squared norms.
// ---------------------------------------------------------------------------
__global__ void rq_prep_kernel(const float* __restrict__ cb) {
    int i = blockIdx.x * blockDim.x + threadIdx.x;
    const int total = NLEV * KCB * DIM;
    if (i < total) {
        int l   = i / (KCB * DIM);
        int rem = i - l * (KCB * DIM);
        int e   = rem >> 7;      // DIM = 128
        int k   = rem & 127;
        g_cbT[l * (DIM * KCB) + k * KCB + e] = cb[i];
    }
    if (i < NLEV * KCB) {
        const float* p = cb + (size_t)i * DIM;
        float s = 0.0f;
        #pragma unroll 1
        for (int k = 0; k < DIM; k++) s = fmaf(p[k], p[k], s);
        g_cnorm[i] = s;
    }
}

// ---------------------------------------------------------------------------
// Main fused RQ kernel.
//   block: 256 threads, 64 rows resident in smem.
//   per level: copy cbT level into smem, fp32 GEMM (packed f32x2 FMA),
//   warp argmin (jax tie-break: lowest index), gather from global codebook,
//   residual update in smem. recon = x - residual_final.
// Thread tile: warp w owns rows w*8..w*8+7; lane owns entries lane*8..lane*8+7.
// ---------------------------------------------------------------------------
extern __shared__ float smem_dyn[];

__global__ void __launch_bounds__(TPB, 1)
rq_main_kernel(const float* __restrict__ x,
               const float* __restrict__ cb,        // [l][e][k] original
               float* __restrict__ out_recon,
               float* __restrict__ out_codes,
               int write_codes) {
    float* shCbT = smem_dyn;                    // DIM*KCB   = 32768 f
    float* shRes = smem_dyn + DIM * KCB;        // ROWS*DIM  =  8192 f
    float* shCn  = shRes + ROWS * DIM;          // KCB       =   256 f

    const int tid   = threadIdx.x;
    const int lane  = tid & 31;
    const int warp  = tid >> 5;
    const long long row0 = (long long)blockIdx.x * ROWS;
    const int rbase = warp * 8;     // 8 warps * 8 rows = 64
    const int ebase = lane * 8;     // 32 lanes * 8 entries = 256

    // ---- load x tile into residual smem (coalesced float4) ----
    const float4* x4   = (const float4*)(x + row0 * DIM);
    float4*       res4 = (float4*)shRes;
    #pragma unroll
    for (int i = 0; i < (ROWS * DIM / 4) / TPB; i++)    // 8 iters
        res4[tid + i * TPB] = x4[tid + i * TPB];

    for (int l = 0; l < NLEV; l++) {
        __syncthreads();   // residual stable + previous-level cbT reads done

        // ---- stage transposed codebook level into smem (coalesced, conflict-free) ----
        {
            const float4* g4 = (const float4*)(g_cbT + (size_t)l * DIM * KCB);
            float4*       s4 = (float4*)shCbT;
            #pragma unroll
            for (int i = 0; i < (DIM * KCB / 4) / TPB; i++)  // 32 iters
                s4[tid + i * TPB] = g4[tid + i * TPB];
            if (tid < KCB) shCn[tid] = g_cnorm[l * KCB + tid];
        }
        __syncthreads();

        // ---- GEMM: dot[r][e] for 8 rows x 8 entries per thread ----
        // acc holds packed f32x2: low lane = entry e, high lane = entry e+1
        unsigned long long acc[8][4];
        #pragma unroll
        for (int r = 0; r < 8; r++)
            #pragma unroll
            for (int j = 0; j < 4; j++) acc[r][j] = 0ull;

        #pragma unroll 2
        for (int k = 0; k < DIM; k += 4) {
            // codebook entry-pairs for 4 consecutive k (2x LDS.128 per k)
            ulonglong2 cA[4], cB[4];
            #pragma unroll
            for (int kk = 0; kk < 4; kk++) {
                const float* p = shCbT + (k + kk) * KCB + ebase;
                cA[kk] = *(const ulonglong2*)p;         // entries e..e+3
                cB[kk] = *(const ulonglong2*)(p + 4);   // entries e+4..e+7
            }
            // residual fragments: 8 rows x 4 k (broadcast LDS.128 per row)
            float4 rf[8];
            #pragma unroll
            for (int r = 0; r < 8; r++)
                rf[r] = *(const float4*)(shRes + (rbase + r) * DIM + k);

            #pragma unroll
            for (int kk = 0; kk < 4; kk++) {
                #pragma unroll
                for (int r = 0; r < 8; r++) {
                    float rv = (&rf[r].x)[kk];
                    unsigned long long rr;
                    asm("mov.b64 %0, {%1, %1};" : "=l"(rr) : "r"(__float_as_uint(rv)));
                    asm("fma.rn.f32x2 %0, %1, %2, %0;" : "+l"(acc[r][0]) : "l"(rr), "l"(cA[kk].x));
                    asm("fma.rn.f32x2 %0, %1, %2, %0;" : "+l"(acc[r][1]) : "l"(rr), "l"(cA[kk].y));
                    asm("fma.rn.f32x2 %0, %1, %2, %0;" : "+l"(acc[r][2]) : "l"(rr), "l"(cB[kk].x));
                    asm("fma.rn.f32x2 %0, %1, %2, %0;" : "+l"(acc[r][3]) : "l"(rr), "l"(cB[kk].y));
                }
            }
        }

        // ---- per-row argmin of dist = -2*dot + cnorm (jax tie-break: first min) ----
        float4 cn0 = *(const float4*)(shCn + ebase);
        float4 cn1 = *(const float4*)(shCn + ebase + 4);
        float cns[8] = {cn0.x, cn0.y, cn0.z, cn0.w, cn1.x, cn1.y, cn1.z, cn1.w};

        int bidx[8];
        #pragma unroll
        for (int r = 0; r < 8; r++) {
            float bestd = 3.402823466e38f;
            int   besti = 0;
            #pragma unroll
            for (int j = 0; j < 8; j++) {
                unsigned long long a = acc[r][j >> 1];
                unsigned u = (j & 1) ? (unsigned)(a >> 32) : (unsigned)(a & 0xffffffffull);
                float dot = __uint_as_float(u);
                // -2*dot is exact in fp32, so fmaf == mul-then-add here (single rounding at add)
                float d = fmaf(-2.0f, dot, cns[j]);
                if (d < bestd) { bestd = d; besti = ebase + j; }
            }
            #pragma unroll
            for (int off = 16; off > 0; off >>= 1) {
                float od = __shfl_xor_sync(0xffffffffu, bestd, off);
                int   oi = __shfl_xor_sync(0xffffffffu, besti, off);
                if (od < bestd || (od == bestd && oi < besti)) { bestd = od; besti = oi; }
            }
            bidx[r] = besti;   // all lanes agree
        }

        // ---- gather selected codeword from global (L2-hot) + residual update ----
        #pragma unroll
        for (int r = 0; r < 8; r++) {
            const float4 cv =
                *(((const float4*)(cb + ((size_t)(l * KCB + bidx[r]) << 7))) + lane);
            float4* rp = ((float4*)(shRes + (rbase + r) * DIM)) + lane;
            float4 rv = *rp;
            rv.x -= cv.x; rv.y -= cv.y; rv.z -= cv.z; rv.w -= cv.w;
            *rp = rv;
            if (write_codes && lane == 0)
                out_codes[(row0 + rbase + r) * NLEV + l] = (float)bidx[r];
        }
    }

    // ---- recon = x - residual_final ----
    __syncthreads();
    float4* o4 = (float4*)(out_recon + row0 * DIM);
    #pragma unroll
    for (int i = 0; i < (ROWS * DIM / 4) / TPB; i++) {
        float4 xv = x4[tid + i * TPB];
        float4 rv = res4[tid + i * TPB];
        o4[tid + i * TPB] = make_float4(xv.x - rv.x, xv.y - rv.y, xv.z - rv.z, xv.w - rv.w);
    }
}

// ---------------------------------------------------------------------------
extern "C" void kernel_launch(void* const* d_in, const int* in_sizes, int n_in,
                              void* d_out, int out_size) {
    const float* x  = (const float*)d_in[0];
    const float* cb = (const float*)d_in[1];
    int nx = in_sizes[0];
    int nc = (n_in > 1) ? in_sizes[1] : 0;
    // robustness: identify codebook input by its size
    if (nx == NLEV * KCB * DIM && nc != NLEV * KCB * DIM) {
        const float* t = x; x = cb; cb = t;
        int ts = nx; nx = nc; nc = ts;
    }
    const int B = nx / DIM;

    float* out       = (float*)d_out;
    float* out_codes = out + (size_t)B * DIM;
    int write_codes  = (out_size >= B * DIM + B * NLEV) ? 1 : 0;

    const int prep_total = NLEV * KCB * DIM;
    rq_prep_kernel<<<(prep_total + TPB - 1) / TPB, TPB>>>(cb);

    size_t smem = (size_t)(DIM * KCB + ROWS * DIM + KCB) * sizeof(float); // 164,864 B
    cudaFuncSetAttribute(rq_main_kernel,
                         cudaFuncAttributeMaxDynamicSharedMemorySize, (int)smem);
    rq_main_kernel<<<B / ROWS, TPB, smem>>>(x, cb, out, out_codes, write_codes);
}

// round 6
// speedup vs baseline: 1.0311x; 1.0311x over previous
#include <cuda_runtime.h>

#define NLEV 4
#define KCB  256
#define DIM  128
#define ROWS 64
#define TPB  256
#define KHALF 64
#define CHUNKF (KHALF * KCB)   // 16384 floats = 64 KB per chunk

// Scratch (allocation-free rule: __device__ globals).
// g_cbT: transposed codebook [l][k][e]; a k-half (64 x 256 floats) is contiguous.
__device__ float g_cbT[NLEV * DIM * KCB];
__device__ float g_cnorm[NLEV * KCB];

// ---------------------------------------------------------------------------
// Prep: build transposed codebook + per-entry squared norms.
// ---------------------------------------------------------------------------
__global__ void rq_prep_kernel(const float* __restrict__ cb) {
    int i = blockIdx.x * blockDim.x + threadIdx.x;
    const int total = NLEV * KCB * DIM;
    if (i < total) {
        int l   = i / (KCB * DIM);
        int rem = i - l * (KCB * DIM);
        int e   = rem >> 7;      // DIM = 128
        int k   = rem & 127;
        g_cbT[l * (DIM * KCB) + k * KCB + e] = cb[i];
    }
    if (i < NLEV * KCB) {
        const float* p = cb + (size_t)i * DIM;
        float s = 0.0f;
        #pragma unroll 1
        for (int k = 0; k < DIM; k++) s = fmaf(p[k], p[k], s);
        g_cnorm[i] = s;
    }
}

__device__ __forceinline__ void cp16(float* s, const float* g) {
    unsigned sa = (unsigned)__cvta_generic_to_shared(s);
    asm volatile("cp.async.cg.shared.global [%0], [%1], 16;" :: "r"(sa), "l"(g));
}

// ---------------------------------------------------------------------------
// Main fused RQ kernel.
//   256 threads, 64 rows resident. Codebook staged in two 64KB k-half chunks,
//   double-buffered via cp.async so staging overlaps the GEMM.
//   Lane entry map: quads {lane*4..+3} and {128+lane*4..+3}  -> 16B lane
//   stride -> conflict-free LDS.128.
// ---------------------------------------------------------------------------
extern __shared__ float smem_dyn[];

__global__ void __launch_bounds__(TPB, 1)
rq_main_kernel(const float* __restrict__ x,
               const float* __restrict__ cb,        // [l][e][k] original
               float* __restrict__ out_recon,
               float* __restrict__ out_codes,
               int write_codes) {
    float* shBuf = smem_dyn;                    // 2 * 16384 floats (double buffer)
    float* shRes = smem_dyn + 2 * CHUNKF;       // ROWS*DIM = 8192 floats
    float* shCn  = shRes + ROWS * DIM;          // NLEV*KCB = 1024 floats (all levels)

    const int tid   = threadIdx.x;
    const int lane  = tid & 31;
    const int warp  = tid >> 5;
    const long long row0 = (long long)blockIdx.x * ROWS;
    const int rbase = warp * 8;      // 8 warps * 8 rows
    const int e0    = lane * 4;      // quad A base; quad B base = 128 + e0

    // all levels' cnorms -> smem (1024 floats, one float4 per thread)
    ((float4*)shCn)[tid] = ((const float4*)g_cnorm)[tid];

    // x tile -> residual smem (coalesced)
    const float4* x4   = (const float4*)(x + row0 * DIM);
    float4*       res4 = (float4*)shRes;
    #pragma unroll
    for (int i = 0; i < (ROWS * DIM / 4) / TPB; i++)   // 8
        res4[tid + i * TPB] = x4[tid + i * TPB];

    // prologue: prefetch chunks 0,1 (level 0, both k-halves)
    #pragma unroll
    for (int c = 0; c < 2; c++) {
        const float* g = g_cbT + (size_t)c * CHUNKF;
        float*       s = shBuf + (c & 1) * CHUNKF;
        #pragma unroll
        for (int i = 0; i < CHUNKF / 4 / TPB; i++)     // 16
            cp16(s + (size_t)(tid + i * TPB) * 4, g + (size_t)(tid + i * TPB) * 4);
        asm volatile("cp.async.commit_group;");
    }

    for (int l = 0; l < NLEV; l++) {
        // acc: packed f32x2 dot accumulators, low lane = even entry of the pair
        unsigned long long acc[8][4];
        #pragma unroll
        for (int r = 0; r < 8; r++) {
            acc[r][0] = 0ull; acc[r][1] = 0ull; acc[r][2] = 0ull; acc[r][3] = 0ull;
        }

        #pragma unroll 1
        for (int h = 0; h < 2; h++) {
            // chunk c = 2l+h. One group was committed per prior half (possibly
            // empty), so "<=1 pending" guarantees chunk c has landed.
            asm volatile("cp.async.wait_group 1;" ::: "memory");
            __syncthreads();

            const float* bufp = shBuf + ((2 * l + h) & 1) * CHUNKF;
            const float* resp = shRes + rbase * DIM + h * KHALF;

            #pragma unroll 2
            for (int k = 0; k < KHALF; k += 4) {
                // codebook quads: 16B lane stride -> conflict-free LDS.128
                ulonglong2 cA[4], cB[4];
                #pragma unroll
                for (int kk = 0; kk < 4; kk++) {
                    const float* p = bufp + (k + kk) * KCB + e0;
                    cA[kk] = *(const ulonglong2*)p;          // entries e0..e0+3
                    cB[kk] = *(const ulonglong2*)(p + 128);  // entries 128+e0..+3
                }
                // residual fragments: broadcast LDS.128 (warp-private rows)
                float4 rf[8];
                #pragma unroll
                for (int r = 0; r < 8; r++)
                    rf[r] = *(const float4*)(resp + r * DIM + k);

                #pragma unroll
                for (int kk = 0; kk < 4; kk++) {
                    #pragma unroll
                    for (int r = 0; r < 8; r++) {
                        float rv = (&rf[r].x)[kk];
                        unsigned long long rr;
                        asm("mov.b64 %0, {%1, %1};" : "=l"(rr) : "r"(__float_as_uint(rv)));
                        asm("fma.rn.f32x2 %0, %1, %2, %0;" : "+l"(acc[r][0]) : "l"(rr), "l"(cA[kk].x));
                        asm("fma.rn.f32x2 %0, %1, %2, %0;" : "+l"(acc[r][1]) : "l"(rr), "l"(cA[kk].y));
                        asm("fma.rn.f32x2 %0, %1, %2, %0;" : "+l"(acc[r][2]) : "l"(rr), "l"(cB[kk].x));
                        asm("fma.rn.f32x2 %0, %1, %2, %0;" : "+l"(acc[r][3]) : "l"(rr), "l"(cB[kk].y));
                    }
                }
            }
            __syncthreads();   // all warps done reading this buffer

            // prefetch chunk c+2 into the buffer just freed; always commit a
            // group (possibly empty) to keep wait_group accounting uniform.
            int c = 2 * l + h + 2;
            if (c < 2 * NLEV) {
                const float* g = g_cbT + (size_t)c * CHUNKF;
                float*       s = shBuf + (c & 1) * CHUNKF;
                #pragma unroll
                for (int i = 0; i < CHUNKF / 4 / TPB; i++)
                    cp16(s + (size_t)(tid + i * TPB) * 4, g + (size_t)(tid + i * TPB) * 4);
            }
            asm volatile("cp.async.commit_group;");
        }

        // ---- per-row argmin of dist = -2*dot + cnorm (jax tie-break: first min) ----
        const float* cnl = shCn + l * KCB;
        float4 cn0 = *(const float4*)(cnl + e0);
        float4 cn1 = *(const float4*)(cnl + 128 + e0);
        float cns[8] = {cn0.x, cn0.y, cn0.z, cn0.w, cn1.x, cn1.y, cn1.z, cn1.w};

        #pragma unroll
        for (int r = 0; r < 8; r++) {
            float bestd = 3.402823466e38f;
            int   besti = 0x7fffffff;
            #pragma unroll
            for (int j = 0; j < 8; j++) {
                unsigned long long a = acc[r][j >> 1];
                unsigned u = (j & 1) ? (unsigned)(a >> 32) : (unsigned)a;
                // -2*dot exact in fp32 -> fmaf == mul-then-add (single rounding)
                float d = fmaf(-2.0f, __uint_as_float(u), cns[j]);
                int idx = (j < 4) ? (e0 + j) : (128 + e0 + (j - 4));
                if (d < bestd) { bestd = d; besti = idx; }
            }
            #pragma unroll
            for (int off = 16; off > 0; off >>= 1) {
                float od = __shfl_xor_sync(0xffffffffu, bestd, off);
                int   oi = __shfl_xor_sync(0xffffffffu, besti, off);
                if (od < bestd || (od == bestd && oi < besti)) { bestd = od; besti = oi; }
            }
            // gather selected codeword from global (L2-hot), update residual
            // (rows are warp-private -> no barrier needed)
            const float4 cv =
                *(((const float4*)(cb + ((size_t)(l * KCB + besti) << 7))) + lane);
            float4* rp = ((float4*)(shRes + (rbase + r) * DIM)) + lane;
            float4 rv = *rp;
            rv.x -= cv.x; rv.y -= cv.y; rv.z -= cv.z; rv.w -= cv.w;
            *rp = rv;
            if (write_codes && lane == 0)
                out_codes[(row0 + rbase + r) * NLEV + l] = (float)besti;
        }
    }

    // ---- recon = x - residual_final ----
    __syncthreads();
    float4* o4 = (float4*)(out_recon + row0 * DIM);
    #pragma unroll
    for (int i = 0; i < (ROWS * DIM / 4) / TPB; i++) {
        float4 xv = x4[tid + i * TPB];
        float4 rv = res4[tid + i * TPB];
        o4[tid + i * TPB] = make_float4(xv.x - rv.x, xv.y - rv.y, xv.z - rv.z, xv.w - rv.w);
    }
}

// ---------------------------------------------------------------------------
extern "C" void kernel_launch(void* const* d_in, const int* in_sizes, int n_in,
                              void* d_out, int out_size) {
    const float* x  = (const float*)d_in[0];
    const float* cb = (const float*)d_in[1];
    int nx = in_sizes[0];
    int nc = (n_in > 1) ? in_sizes[1] : 0;
    if (nx == NLEV * KCB * DIM && nc != NLEV * KCB * DIM) {
        const float* t = x; x = cb; cb = t;
        int ts = nx; nx = nc; nc = ts;
    }
    const int B = nx / DIM;

    float* out       = (float*)d_out;
    float* out_codes = out + (size_t)B * DIM;
    int write_codes  = (out_size >= B * DIM + B * NLEV) ? 1 : 0;

    const int prep_total = NLEV * KCB * DIM;
    rq_prep_kernel<<<(prep_total + TPB - 1) / TPB, TPB>>>(cb);

    size_t smem = (size_t)(2 * CHUNKF + ROWS * DIM + NLEV * KCB) * sizeof(float); // 167,936 B
    cudaFuncSetAttribute(rq_main_kernel,
                         cudaFuncAttributeMaxDynamicSharedMemorySize, (int)smem);
    rq_main_kernel<<<B / ROWS, TPB, smem>>>(x, cb, out, out_codes, write_codes);
}

// round 7
// speedup vs baseline: 1.0623x; 1.0303x over previous
#include <cuda_runtime.h>

#define NLEV 4
#define KCB  256
#define DIM  128
#define ROWS 64
#define TPB  256
#define KQ    32                 // k-quarter per staged chunk
#define CHUNKF (KQ * KCB)        // 8192 floats = 32 KB per chunk
#define NCHUNK (NLEV * 4)        // 16 chunks total

// Scratch (allocation-free rule: __device__ globals).
// g_cbT: transposed codebook [l][k][e]; a k-quarter (32 x 256 floats) is contiguous.
__device__ float g_cbT[NLEV * DIM * KCB];
__device__ float g_cnorm[NLEV * KCB];

// ---------------------------------------------------------------------------
// Prep: build transposed codebook + per-entry squared norms.
// ---------------------------------------------------------------------------
__global__ void rq_prep_kernel(const float* __restrict__ cb) {
    int i = blockIdx.x * blockDim.x + threadIdx.x;
    const int total = NLEV * KCB * DIM;
    if (i < total) {
        int l   = i / (KCB * DIM);
        int rem = i - l * (KCB * DIM);
        int e   = rem >> 7;      // DIM = 128
        int k   = rem & 127;
        g_cbT[l * (DIM * KCB) + k * KCB + e] = cb[i];
    }
    if (i < NLEV * KCB) {
        const float* p = cb + (size_t)i * DIM;
        float s = 0.0f;
        #pragma unroll 1
        for (int k = 0; k < DIM; k++) s = fmaf(p[k], p[k], s);
        g_cnorm[i] = s;
    }
}

__device__ __forceinline__ void cp16(float* s, const float* g) {
    unsigned sa = (unsigned)__cvta_generic_to_shared(s);
    asm volatile("cp.async.cg.shared.global [%0], [%1], 16;" :: "r"(sa), "l"(g));
}

// ---------------------------------------------------------------------------
// Main fused RQ kernel — 2 blocks/SM (smem 100.25 KB, regs capped at 128).
//   256 threads, 64 rows resident. Codebook staged in 32 KB k-quarter chunks,
//   double-buffered via cp.async. Lane entry map: quads {lane*4..+3} and
//   {128+lane*4..+3} -> 16B lane stride -> conflict-free LDS.128.
// ---------------------------------------------------------------------------
extern __shared__ float smem_dyn[];

__global__ void __launch_bounds__(TPB, 2)
rq_main_kernel(const float* __restrict__ x,
               const float* __restrict__ cb,        // [l][e][k] original
               float* __restrict__ out_recon,
               float* __restrict__ out_codes,
               int write_codes) {
    float* shBuf = smem_dyn;                    // 2 * 8192 floats (double buffer)
    float* shRes = smem_dyn + 2 * CHUNKF;       // ROWS*DIM = 8192 floats
    float* shCn  = shRes + ROWS * DIM;          // NLEV*KCB = 1024 floats

    const int tid   = threadIdx.x;
    const int lane  = tid & 31;
    const int warp  = tid >> 5;
    const long long row0 = (long long)blockIdx.x * ROWS;
    const int rbase = warp * 8;      // 8 warps * 8 rows
    const int e0    = lane * 4;      // quad A base; quad B base = 128 + e0

    // all levels' cnorms -> smem
    ((float4*)shCn)[tid] = ((const float4*)g_cnorm)[tid];

    // x tile -> residual smem (coalesced)
    const float4* x4   = (const float4*)(x + row0 * DIM);
    float4*       res4 = (float4*)shRes;
    #pragma unroll
    for (int i = 0; i < (ROWS * DIM / 4) / TPB; i++)   // 8
        res4[tid + i * TPB] = x4[tid + i * TPB];

    // prologue: prefetch chunks 0,1
    #pragma unroll
    for (int c = 0; c < 2; c++) {
        const float* g = g_cbT + (size_t)c * CHUNKF;
        float*       s = shBuf + (c & 1) * CHUNKF;
        #pragma unroll
        for (int i = 0; i < CHUNKF / 4 / TPB; i++)     // 8
            cp16(s + (size_t)(tid + i * TPB) * 4, g + (size_t)(tid + i * TPB) * 4);
        asm volatile("cp.async.commit_group;");
    }

    for (int l = 0; l < NLEV; l++) {
        // packed f32x2 dot accumulators, low lane = even entry of the pair
        unsigned long long acc[8][4];
        #pragma unroll
        for (int r = 0; r < 8; r++) {
            acc[r][0] = 0ull; acc[r][1] = 0ull; acc[r][2] = 0ull; acc[r][3] = 0ull;
        }

        #pragma unroll 1
        for (int q = 0; q < 4; q++) {
            const int c = 4 * l + q;
            // one group committed per prior quarter -> "<=1 pending" => chunk c landed
            asm volatile("cp.async.wait_group 1;" ::: "memory");
            __syncthreads();

            const float* bufp = shBuf + (c & 1) * CHUNKF + e0;
            const float* resp = shRes + rbase * DIM + q * KQ;

            #pragma unroll 2
            for (int k = 0; k < KQ; k += 4) {
                // residual fragments: broadcast LDS.128 (warp-private rows)
                float4 rf[8];
                #pragma unroll
                for (int r = 0; r < 8; r++)
                    rf[r] = *(const float4*)(resp + r * DIM + k);

                #pragma unroll
                for (int kk = 0; kk < 4; kk++) {
                    // codebook quads loaded per-kk (keeps regs <= 128 for occ=2)
                    const float* p = bufp + (k + kk) * KCB;
                    ulonglong2 cA = *(const ulonglong2*)p;          // e0..e0+3
                    ulonglong2 cB = *(const ulonglong2*)(p + 128);  // 128+e0..+3
                    #pragma unroll
                    for (int r = 0; r < 8; r++) {
                        float rv = (&rf[r].x)[kk];
                        unsigned long long rr;
                        asm("mov.b64 %0, {%1, %1};" : "=l"(rr) : "r"(__float_as_uint(rv)));
                        asm("fma.rn.f32x2 %0, %1, %2, %0;" : "+l"(acc[r][0]) : "l"(rr), "l"(cA.x));
                        asm("fma.rn.f32x2 %0, %1, %2, %0;" : "+l"(acc[r][1]) : "l"(rr), "l"(cA.y));
                        asm("fma.rn.f32x2 %0, %1, %2, %0;" : "+l"(acc[r][2]) : "l"(rr), "l"(cB.x));
                        asm("fma.rn.f32x2 %0, %1, %2, %0;" : "+l"(acc[r][3]) : "l"(rr), "l"(cB.y));
                    }
                }
            }
            __syncthreads();   // all warps done reading this buffer

            // prefetch chunk c+2 into the freed buffer; always commit a group
            // (possibly empty) to keep wait_group accounting uniform.
            if (c + 2 < NCHUNK) {
                const float* g = g_cbT + (size_t)(c + 2) * CHUNKF;
                float*       s = shBuf + (c & 1) * CHUNKF;
                #pragma unroll
                for (int i = 0; i < CHUNKF / 4 / TPB; i++)
                    cp16(s + (size_t)(tid + i * TPB) * 4, g + (size_t)(tid + i * TPB) * 4);
            }
            asm volatile("cp.async.commit_group;");
        }

        // ---- per-row argmin of dist = -2*dot + cnorm (jax tie-break: first min) ----
        const float* cnl = shCn + l * KCB;
        float4 cn0 = *(const float4*)(cnl + e0);
        float4 cn1 = *(const float4*)(cnl + 128 + e0);
        float cns[8] = {cn0.x, cn0.y, cn0.z, cn0.w, cn1.x, cn1.y, cn1.z, cn1.w};

        #pragma unroll
        for (int r = 0; r < 8; r++) {
            float bestd = 3.402823466e38f;
            int   besti = 0x7fffffff;
            #pragma unroll
            for (int j = 0; j < 8; j++) {
                unsigned long long a = acc[r][j >> 1];
                unsigned u = (j & 1) ? (unsigned)(a >> 32) : (unsigned)a;
                // -2*dot exact in fp32 -> fmaf == mul-then-add (single rounding)
                float d = fmaf(-2.0f, __uint_as_float(u), cns[j]);
                int idx = (j < 4) ? (e0 + j) : (128 + e0 + (j - 4));
                if (d < bestd) { bestd = d; besti = idx; }
            }
            #pragma unroll
            for (int off = 16; off > 0; off >>= 1) {
                float od = __shfl_xor_sync(0xffffffffu, bestd, off);
                int   oi = __shfl_xor_sync(0xffffffffu, besti, off);
                if (od < bestd || (od == bestd && oi < besti)) { bestd = od; besti = oi; }
            }
            // gather selected codeword from global (L2-hot), update residual
            // (rows are warp-private -> no barrier needed)
            const float4 cv =
                *(((const float4*)(cb + ((size_t)(l * KCB + besti) << 7))) + lane);
            float4* rp = ((float4*)(shRes + (rbase + r) * DIM)) + lane;
            float4 rv = *rp;
            rv.x -= cv.x; rv.y -= cv.y; rv.z -= cv.z; rv.w -= cv.w;
            *rp = rv;
            if (write_codes && lane == 0)
                out_codes[(row0 + rbase + r) * NLEV + l] = (float)besti;
        }
    }

    // ---- recon = x - residual_final ----
    __syncthreads();
    float4* o4 = (float4*)(out_recon + row0 * DIM);
    #pragma unroll
    for (int i = 0; i < (ROWS * DIM / 4) / TPB; i++) {
        float4 xv = x4[tid + i * TPB];
        float4 rv = res4[tid + i * TPB];
        o4[tid + i * TPB] = make_float4(xv.x - rv.x, xv.y - rv.y, xv.z - rv.z, xv.w - rv.w);
    }
}

// ---------------------------------------------------------------------------
extern "C" void kernel_launch(void* const* d_in, const int* in_sizes, int n_in,
                              void* d_out, int out_size) {
    const float* x  = (const float*)d_in[0];
    const float* cb = (const float*)d_in[1];
    int nx = in_sizes[0];
    int nc = (n_in > 1) ? in_sizes[1] : 0;
    if (nx == NLEV * KCB * DIM && nc != NLEV * KCB * DIM) {
        const float* t = x; x = cb; cb = t;
        int ts = nx; nx = nc; nc = ts;
    }
    const int B = nx / DIM;

    float* out       = (float*)d_out;
    float* out_codes = out + (size_t)B * DIM;
    int write_codes  = (out_size >= B * DIM + B * NLEV) ? 1 : 0;

    const int prep_total = NLEV * KCB * DIM;
    rq_prep_kernel<<<(prep_total + TPB - 1) / TPB, TPB>>>(cb);

    size_t smem = (size_t)(2 * CHUNKF + ROWS * DIM + NLEV * KCB) * sizeof(float); // 102,400 B
    cudaFuncSetAttribute(rq_main_kernel,
                         cudaFuncAttributeMaxDynamicSharedMemorySize, (int)smem);
    rq_main_kernel<<<B / ROWS, TPB, smem>>>(x, cb, out, out_codes, write_codes);
}

// round 8
// speedup vs baseline: 1.0852x; 1.0215x over previous
#include <cuda_runtime.h>

#define NLEV 4
#define KCB  256
#define DIM  128
#define ROWS 64
#define TPB  256
#define KQ    32                 // k-quarter per staged chunk
#define CHUNKF (KQ * KCB)        // 8192 floats = 32 KB per chunk
#define NCHUNK (NLEV * 4)        // 16 chunks total

// Scratch (allocation-free rule: __device__ globals).
__device__ float g_cbT[NLEV * DIM * KCB];   // [l][k][e], k-quarter contiguous
__device__ float g_cnorm[NLEV * KCB];

// ---------------------------------------------------------------------------
// Prep: transposed codebook + per-entry squared norms.
// ---------------------------------------------------------------------------
__global__ void rq_prep_kernel(const float* __restrict__ cb) {
    int i = blockIdx.x * blockDim.x + threadIdx.x;
    const int total = NLEV * KCB * DIM;
    if (i < total) {
        int l   = i / (KCB * DIM);
        int rem = i - l * (KCB * DIM);
        int e   = rem >> 7;
        int k   = rem & 127;
        g_cbT[l * (DIM * KCB) + k * KCB + e] = cb[i];
    }
    if (i < NLEV * KCB) {
        const float* p = cb + (size_t)i * DIM;
        float s = 0.0f;
        #pragma unroll 1
        for (int k = 0; k < DIM; k++) s = fmaf(p[k], p[k], s);
        g_cnorm[i] = s;
    }
}

__device__ __forceinline__ void cp16(float* s, const float* g) {
    unsigned sa = (unsigned)__cvta_generic_to_shared(s);
    asm volatile("cp.async.cg.shared.global [%0], [%1], 16;" :: "r"(sa), "l"(g));
}

// FFMA2 block: 8 rows x 4 entry-pairs against one k of codebook.
// Accumulation order over k is strictly ascending (phases consume k in order),
// identical to the reference-matching kernels of prior rounds.
#define GEMM_STEP(RV, CA, CB)                                                          \
    {                                                                                  \
        _Pragma("unroll")                                                              \
        for (int r = 0; r < 8; r++) {                                                  \
            unsigned long long rr;                                                     \
            asm("mov.b64 %0, {%1, %1};" : "=l"(rr) : "r"(__float_as_uint(RV[r])));     \
            asm("fma.rn.f32x2 %0, %1, %2, %0;" : "+l"(acc[r][0]) : "l"(rr), "l"(CA.x));\
            asm("fma.rn.f32x2 %0, %1, %2, %0;" : "+l"(acc[r][1]) : "l"(rr), "l"(CA.y));\
            asm("fma.rn.f32x2 %0, %1, %2, %0;" : "+l"(acc[r][2]) : "l"(rr), "l"(CB.x));\
            asm("fma.rn.f32x2 %0, %1, %2, %0;" : "+l"(acc[r][3]) : "l"(rr), "l"(CB.y));\
        }                                                                              \
    }

#define LOAD_C(CA, CB, KI)                                                             \
    {                                                                                  \
        const float* _p = bufp + (KI) * KCB;                                           \
        CA = *(const ulonglong2*)_p;                                                   \
        CB = *(const ulonglong2*)(_p + 128);                                           \
    }

#define LOAD_RF(RF, KI)                                                                \
    {                                                                                  \
        _Pragma("unroll")                                                              \
        for (int r = 0; r < 8; r++)                                                    \
            RF[r] = *(const float2*)(resp + r * DIM + (KI));                           \
    }

// ---------------------------------------------------------------------------
// Main fused RQ kernel — 2 blocks/SM; 4-phase software-pipelined inner loop.
// ---------------------------------------------------------------------------
extern __shared__ float smem_dyn[];

__global__ void __launch_bounds__(TPB, 2)
rq_main_kernel(const float* __restrict__ x,
               const float* __restrict__ cb,        // [l][e][k] original
               float* __restrict__ out_recon,
               float* __restrict__ out_codes,
               int write_codes) {
    float* shBuf = smem_dyn;                    // 2 * 8192 floats (double buffer)
    float* shRes = smem_dyn + 2 * CHUNKF;       // ROWS*DIM = 8192 floats
    float* shCn  = shRes + ROWS * DIM;          // NLEV*KCB = 1024 floats

    const int tid   = threadIdx.x;
    const int lane  = tid & 31;
    const int warp  = tid >> 5;
    const long long row0 = (long long)blockIdx.x * ROWS;
    const int rbase = warp * 8;      // 8 warps * 8 rows
    const int e0    = lane * 4;      // quad A base; quad B base = 128 + e0

    ((float4*)shCn)[tid] = ((const float4*)g_cnorm)[tid];

    const float4* x4   = (const float4*)(x + row0 * DIM);
    float4*       res4 = (float4*)shRes;
    #pragma unroll
    for (int i = 0; i < (ROWS * DIM / 4) / TPB; i++)   // 8
        res4[tid + i * TPB] = x4[tid + i * TPB];

    // prologue: prefetch chunks 0,1
    #pragma unroll
    for (int c = 0; c < 2; c++) {
        const float* g = g_cbT + (size_t)c * CHUNKF;
        float*       s = shBuf + (c & 1) * CHUNKF;
        #pragma unroll
        for (int i = 0; i < CHUNKF / 4 / TPB; i++)     // 8
            cp16(s + (size_t)(tid + i * TPB) * 4, g + (size_t)(tid + i * TPB) * 4);
        asm volatile("cp.async.commit_group;");
    }

    for (int l = 0; l < NLEV; l++) {
        unsigned long long acc[8][4];
        #pragma unroll
        for (int r = 0; r < 8; r++) {
            acc[r][0] = 0ull; acc[r][1] = 0ull; acc[r][2] = 0ull; acc[r][3] = 0ull;
        }

        #pragma unroll 1
        for (int q = 0; q < 4; q++) {
            const int c = 4 * l + q;
            asm volatile("cp.async.wait_group 1;" ::: "memory");
            __syncthreads();

            const float* bufp = shBuf + (c & 1) * CHUNKF + e0;
            const float* resp = shRes + rbase * DIM + q * KQ;

            // 4-phase pipeline: every LDS lands one FFMA2 block before use.
            float2 rfA[8], rfB[8];
            ulonglong2 c0A, c0B, c1A, c1B;
            float rvx[8];
            LOAD_RF(rfA, 0);
            LOAD_C(c0A, c0B, 0);

            #pragma unroll 2
            for (int k = 0; k < KQ; k += 4) {
                // phase 0: consume k with c0/rfA.x, prefetch c(k+1)
                LOAD_C(c1A, c1B, k + 1);
                #pragma unroll
                for (int r = 0; r < 8; r++) rvx[r] = rfA[r].x;
                GEMM_STEP(rvx, c0A, c0B);
                // phase 1: consume k+1 with c1/rfA.y, prefetch c(k+2), rf(k+2)
                LOAD_C(c0A, c0B, k + 2);
                LOAD_RF(rfB, k + 2);
                #pragma unroll
                for (int r = 0; r < 8; r++) rvx[r] = rfA[r].y;
                GEMM_STEP(rvx, c1A, c1B);
                // phase 2: consume k+2 with c0/rfB.x, prefetch c(k+3)
                LOAD_C(c1A, c1B, k + 3);
                #pragma unroll
                for (int r = 0; r < 8; r++) rvx[r] = rfB[r].x;
                GEMM_STEP(rvx, c0A, c0B);
                // phase 3: consume k+3 with c1/rfB.y, prefetch c(k+4), rf(k+4)
                int kn = (k + 4 < KQ) ? (k + 4) : 0;   // tail: harmless reload
                LOAD_C(c0A, c0B, kn);
                LOAD_RF(rfA, kn);
                #pragma unroll
                for (int r = 0; r < 8; r++) rvx[r] = rfB[r].y;
                GEMM_STEP(rvx, c1A, c1B);
            }
            __syncthreads();   // all warps done reading this buffer

            if (c + 2 < NCHUNK) {
                const float* g = g_cbT + (size_t)(c + 2) * CHUNKF;
                float*       s = shBuf + (c & 1) * CHUNKF;
                #pragma unroll
                for (int i = 0; i < CHUNKF / 4 / TPB; i++)
                    cp16(s + (size_t)(tid + i * TPB) * 4, g + (size_t)(tid + i * TPB) * 4);
            }
            asm volatile("cp.async.commit_group;");
        }

        // ---- per-row argmin of dist = -2*dot + cnorm (jax tie-break: first min) ----
        const float* cnl = shCn + l * KCB;
        float4 cn0 = *(const float4*)(cnl + e0);
        float4 cn1 = *(const float4*)(cnl + 128 + e0);
        float cns[8] = {cn0.x, cn0.y, cn0.z, cn0.w, cn1.x, cn1.y, cn1.z, cn1.w};

        #pragma unroll
        for (int r = 0; r < 8; r++) {
            float bestd = 3.402823466e38f;
            int   besti = 0x7fffffff;
            #pragma unroll
            for (int j = 0; j < 8; j++) {
                unsigned long long a = acc[r][j >> 1];
                unsigned u = (j & 1) ? (unsigned)(a >> 32) : (unsigned)a;
                float d = fmaf(-2.0f, __uint_as_float(u), cns[j]);
                int idx = (j < 4) ? (e0 + j) : (128 + e0 + (j - 4));
                if (d < bestd) { bestd = d; besti = idx; }
            }
            #pragma unroll
            for (int off = 16; off > 0; off >>= 1) {
                float od = __shfl_xor_sync(0xffffffffu, bestd, off);
                int   oi = __shfl_xor_sync(0xffffffffu, besti, off);
                if (od < bestd || (od == bestd && oi < besti)) { bestd = od; besti = oi; }
            }
            const float4 cv =
                *(((const float4*)(cb + ((size_t)(l * KCB + besti) << 7))) + lane);
            float4* rp = ((float4*)(shRes + (rbase + r) * DIM)) + lane;
            float4 rv = *rp;
            rv.x -= cv.x; rv.y -= cv.y; rv.z -= cv.z; rv.w -= cv.w;
            *rp = rv;
            if (write_codes && lane == 0)
                out_codes[(row0 + rbase + r) * NLEV + l] = (float)besti;
        }
    }

    // ---- recon = x - residual_final ----
    __syncthreads();
    float4* o4 = (float4*)(out_recon + row0 * DIM);
    #pragma unroll
    for (int i = 0; i < (ROWS * DIM / 4) / TPB; i++) {
        float4 xv = x4[tid + i * TPB];
        float4 rv = res4[tid + i * TPB];
        o4[tid + i * TPB] = make_float4(xv.x - rv.x, xv.y - rv.y, xv.z - rv.z, xv.w - rv.w);
    }
}

// ---------------------------------------------------------------------------
extern "C" void kernel_launch(void* const* d_in, const int* in_sizes, int n_in,
                              void* d_out, int out_size) {
    const float* x  = (const float*)d_in[0];
    const float* cb = (const float*)d_in[1];
    int nx = in_sizes[0];
    int nc = (n_in > 1) ? in_sizes[1] : 0;
    if (nx == NLEV * KCB * DIM && nc != NLEV * KCB * DIM) {
        const float* t = x; x = cb; cb = t;
        int ts = nx; nx = nc; nc = ts;
    }
    const int B = nx / DIM;

    float* out       = (float*)d_out;
    float* out_codes = out + (size_t)B * DIM;
    int write_codes  = (out_size >= B * DIM + B * NLEV) ? 1 : 0;

    const int prep_total = NLEV * KCB * DIM;
    rq_prep_kernel<<<(prep_total + TPB - 1) / TPB, TPB>>>(cb);

    size_t smem = (size_t)(2 * CHUNKF + ROWS * DIM + NLEV * KCB) * sizeof(float); // 102,400 B
    cudaFuncSetAttribute(rq_main_kernel,
                         cudaFuncAttributeMaxDynamicSharedMemorySize, (int)smem);
    rq_main_kernel<<<B / ROWS, TPB, smem>>>(x, cb, out, out_codes, write_codes);
}